// round 6
// baseline (speedup 1.0000x reference)
#include <cuda_runtime.h>
#include <cuda_bf16.h>
#include <math.h>

// Fixed shapes: N = 12288
#define NPTS  12288
#define M     20           // cells per axis in warped (≈uniform) space
#define M3    8000
#define NB    125          // 5^3 bricks of 4^3 cells; NB < 148 SMs -> co-resident
#define TPB   128
#define CAP   1024         // halo smem capacity (expected ~332 points)
#define FINF  (3.0e38f)

// Device scratch (no allocations). g_hist / g_bar are zero at module load;
// the kernel restores them to zero every run (replay-invariant).
__device__ float4 g_sorted[NPTS];
__device__ int    g_hist[M3];
__device__ int    g_cursor[M3];
__device__ int    g_cellStart[M3 + 1];
__device__ int    g_cellOf[NPTS];
__device__ int    g_bar[4];

// Cheap monotone quantile map: logistic approx of the gaussian CDF.
// Only monotonicity + rough uniformity matter; must be identical everywhere.
__device__ __forceinline__ int binf(float x) {
    float e = exp2f(-2.4554f * x);          // 2^(-1.702x/ln2)
    float F = 1.0f / (1.0f + e);            // in (0,1)
    int c = (int)(F * 20.0f);
    return min(max(c, 0), M - 1);
}

// ascending insert of d into m1<=m2<=m3
__device__ __forceinline__ void ins3(float d, float& m1, float& m2, float& m3) {
    float t1 = fmaxf(d, m1);  m1 = fminf(d, m1);
    float t2 = fmaxf(t1, m2); m2 = fminf(t1, m2);
    m3 = fminf(t2, m3);
}

// grid-wide barrier: producer release-fence + count; consumer volatile spin.
__device__ __forceinline__ void gbar(int idx) {
    __syncthreads();
    if (threadIdx.x == 0) {
        __threadfence();
        atomicAdd(&g_bar[idx], 1);
        volatile int* p = &g_bar[idx];
        while (*p < NB) { }
        __threadfence();
    }
    __syncthreads();
}

__global__ __launch_bounds__(TPB)
void gauss_fused(const float* __restrict__ pts,
                 const float* __restrict__ quat,
                 float* __restrict__ out) {
    const int tid = threadIdx.x;
    const int b   = blockIdx.x;

    // ================= Phase 1: bin =================
    const int i = b * TPB + tid;          // 16000 threads >= NPTS, one shot
    if (i < NPTS) {
        float x = pts[3 * i + 0], y = pts[3 * i + 1], z = pts[3 * i + 2];
        int c = (binf(z) * M + binf(y)) * M + binf(x);
        g_cellOf[i] = c;
        atomicAdd(&g_hist[c], 1);
    }
    gbar(0);

    // ================= Phase 2: exclusive scan (block 0) =================
    __shared__ int ssum[TPB];
    if (b == 0) {
        const int base = tid * 64;        // 128*64 = 8192 >= M3
        int s = 0;
        #pragma unroll 8
        for (int k = 0; k < 64; ++k) {
            int c = base + k;
            if (c < M3) s += g_hist[c];
        }
        ssum[tid] = s;
        __syncthreads();
        for (int off = 1; off < TPB; off <<= 1) {
            int t = (tid >= off) ? ssum[tid - off] : 0;
            __syncthreads();
            ssum[tid] += t;
            __syncthreads();
        }
        int run = ssum[tid] - s;
        for (int k = 0; k < 64; ++k) {
            int c = base + k;
            if (c < M3) {
                int h = g_hist[c];
                g_hist[c] = 0;            // restore zero-invariant for replay
                g_cellStart[c] = run;
                g_cursor[c]    = run;
                run += h;
            }
        }
        if (tid == 0) g_cellStart[M3] = NPTS;
    }
    gbar(1);

    // ================= Phase 3: scatter =================
    if (i < NPTS) {
        int c = g_cellOf[i];
        int pos = atomicAdd(&g_cursor[c], 1);
        g_sorted[pos] = make_float4(pts[3 * i + 0], pts[3 * i + 1],
                                    pts[3 * i + 2], __int_as_float(i));
    }
    gbar(2);

    // ================= Phase 4: brick NN + covariance =================
    const int Bx = b % 5, By = (b / 5) % 5, Bz = b / 25;
    const int hx0 = max(4 * Bx - 1, 0), hx1 = min(4 * Bx + 4, M - 1);
    const int hy0 = max(4 * By - 1, 0), hy1 = min(4 * By + 4, M - 1);
    const int hz0 = max(4 * Bz - 1, 0), hz1 = min(4 * Bz + 4, M - 1);
    const int wy = hy1 - hy0 + 1;
    const int nrows = (hz1 - hz0 + 1) * wy;      // <= 36 halo rows

    __shared__ float4 sPts[CAP];
    __shared__ int sRowGS[36], sRowSS[37], sLen[36];
    __shared__ int gHomeGS[16], sHLen[16], sHomeSS[17];

    if (tid < nrows) {
        int zz = hz0 + tid / wy, yy = hy0 + tid % wy;
        int rowbase = (zz * M + yy) * M;
        int gs = g_cellStart[rowbase + hx0];
        int ge = g_cellStart[rowbase + hx1 + 1];
        sRowGS[tid] = gs;
        sLen[tid]   = ge - gs;
    }
    __syncthreads();
    if (tid == 0) {
        int run = 0;
        for (int r = 0; r < nrows; ++r) { sRowSS[r] = run; run += sLen[r]; }
        sRowSS[nrows] = run;
    }
    __syncthreads();
    const int TH = sRowSS[nrows];
    const bool ok = (TH <= CAP);                 // halo fits in smem

    // home-row tables (16 rows of 4 home cells)
    if (tid < 16) {
        int zz = 4 * Bz + tid / 4, yy = 4 * By + tid % 4;
        int rowbase = (zz * M + yy) * M;
        int gsH = g_cellStart[rowbase + 4 * Bx];
        int geH = g_cellStart[rowbase + 4 * Bx + 4];
        gHomeGS[tid] = gsH;
        sHLen[tid]   = geH - gsH;
    }
    // halo copy into smem
    if (ok) {
        for (int f = tid; f < TH; f += TPB) {
            int r = 0;
            while (sRowSS[r + 1] <= f) ++r;
            sPts[f] = g_sorted[sRowGS[r] + (f - sRowSS[r])];
        }
    }
    __syncthreads();
    if (tid == 0) {
        int run = 0;
        for (int k = 0; k < 16; ++k) { sHomeSS[k] = run; run += sHLen[k]; }
        sHomeSS[16] = run;
    }
    __syncthreads();
    const int HT = sHomeSS[16];

    for (int h = tid; h < HT; h += TPB) {
        int k = 0;
        while (sHomeSS[k + 1] <= h) ++k;
        const float4 me = g_sorted[gHomeGS[k] + (h - sHomeSS[k])];
        const float x = me.x, y = me.y, z = me.z;
        const int myi = __float_as_int(me.w);

        const int cx = binf(x), cy = binf(y), cz = binf(z);
        const int lxT = max(cx - 1, 0), hxT = min(cx + 1, M - 1);
        const int lyT = max(cy - 1, 0), hyT = min(cy + 1, M - 1);
        const int lzT = max(cz - 1, 0), hzT = min(cz + 1, M - 1);

        float m1 = FINF, m2 = FINF, m3 = FINF;

        // ---- 27-cell scan (smem fast path) ----
        for (int zz = lzT; zz <= hzT; ++zz)
            for (int yy = lyT; yy <= hyT; ++yy) {
                int rowbase = (zz * M + yy) * M;
                int a0 = g_cellStart[rowbase + lxT];
                int a1 = g_cellStart[rowbase + hxT + 1];
                if (ok) {
                    int sb = sRowSS[(zz - hz0) * wy + (yy - hy0)]
                           - sRowGS[(zz - hz0) * wy + (yy - hy0)];
                    for (int t = a0; t < a1; ++t) {
                        float4 q = sPts[sb + t];
                        if (__float_as_int(q.w) != myi) {
                            float dx = x - q.x, dy = y - q.y, dz = z - q.z;
                            ins3(fmaf(dz, dz, fmaf(dy, dy, dx * dx)), m1, m2, m3);
                        }
                    }
                } else {
                    for (int t = a0; t < a1; ++t) {
                        float4 q = g_sorted[t];
                        if (__float_as_int(q.w) != myi) {
                            float dx = x - q.x, dy = y - q.y, dz = z - q.z;
                            ins3(fmaf(dz, dz, fmaf(dy, dy, dx * dx)), m1, m2, m3);
                        }
                    }
                }
            }

        // ---- exactness pass: ball-box minus scanned 27-box (global, rare)
        // found<3 => m3=FINF => box saturates to whole grid => full scan.
        {
            float rad = sqrtf(m3) * 1.0001f;
            int nlx = binf(x - rad), nhx = binf(x + rad);
            int nly = binf(y - rad), nhy = binf(y + rad);
            int nlz = binf(z - rad), nhz = binf(z + rad);
            bool covered = (nlx >= lxT) && (nhx <= hxT) && (nly >= lyT) &&
                           (nhy <= hyT) && (nlz >= lzT) && (nhz <= hzT);
            if (!covered) {
                for (int zz = nlz; zz <= nhz; ++zz)
                    for (int yy = nly; yy <= nhy; ++yy) {
                        int rowbase = (zz * M + yy) * M;
                        bool inRow = (zz >= lzT && zz <= hzT &&
                                      yy >= lyT && yy <= hyT);
                        int a = nlx, bb = inRow ? min(lxT - 1, nhx) : nhx;
                        for (int pass = 0; pass < 2; ++pass) {
                            if (a <= bb) {
                                int s0 = g_cellStart[rowbase + a];
                                int e0 = g_cellStart[rowbase + bb + 1];
                                for (int t = s0; t < e0; ++t) {
                                    float4 q = g_sorted[t];
                                    if (__float_as_int(q.w) != myi) {
                                        float dx = x - q.x, dy = y - q.y,
                                              dz = z - q.z;
                                        ins3(fmaf(dz, dz, fmaf(dy, dy, dx * dx)),
                                             m1, m2, m3);
                                    }
                                }
                            }
                            if (!inRow) break;
                            a = max(hxT + 1, nlx); bb = nhx;
                        }
                    }
            }
        }

        // ---- scale + covariance ----
        float d1 = sqrtf(m1), d2s = sqrtf(m2), d3s = sqrtf(m3);
        float mean = (d1 + d2s + d3s) * (1.0f / 3.0f);
        float s = 0.001f * fmaxf(mean, 1e-5f);

        float qr = quat[4 * myi + 0];
        float qx = quat[4 * myi + 1];
        float qy = quat[4 * myi + 2];
        float qz = quat[4 * myi + 3];
        float inv = rsqrtf(qr * qr + qx * qx + qy * qy + qz * qz);
        qr *= inv; qx *= inv; qy *= inv; qz *= inv;

        float R00 = 1.0f - 2.0f * (qy * qy + qz * qz);
        float R01 = 2.0f * (qx * qy - qr * qz);
        float R02 = 2.0f * (qx * qz + qr * qy);
        float R10 = 2.0f * (qx * qy + qr * qz);
        float R11 = 1.0f - 2.0f * (qx * qx + qz * qz);
        float R12 = 2.0f * (qy * qz - qr * qx);
        float R20 = 2.0f * (qx * qz - qr * qy);
        float R21 = 2.0f * (qy * qz + qr * qx);
        float R22 = 1.0f - 2.0f * (qx * qx + qy * qy);

        float M00 = s * R00, M01 = s * R01, M02 = s * R02;
        float M10 = s * R10, M11 = s * R11, M12 = s * R12;
        float M20 = s * R20, M21 = s * R21, M22 = s * R22;

        float c00 = M00 * M00 + M01 * M01 + M02 * M02;
        float c01 = M00 * M10 + M01 * M11 + M02 * M12;
        float c02 = M00 * M20 + M01 * M21 + M02 * M22;
        float c11 = M10 * M10 + M11 * M11 + M12 * M12;
        float c12 = M10 * M20 + M11 * M21 + M12 * M22;
        float c22 = M20 * M20 + M21 * M21 + M22 * M22;

        float* o = out + (size_t)myi * 9;
        o[0] = c00; o[1] = c01; o[2] = c02;
        o[3] = c01; o[4] = c11; o[5] = c12;
        o[6] = c02; o[7] = c12; o[8] = c22;
    }

    // ---- arrival counter: last block resets all barriers for next replay ----
    __syncthreads();
    if (tid == 0) {
        __threadfence();
        int old = atomicAdd(&g_bar[3], 1);
        if (old == NB - 1) {
            g_bar[0] = 0; g_bar[1] = 0; g_bar[2] = 0; g_bar[3] = 0;
            __threadfence();
        }
    }
}

extern "C" void kernel_launch(void* const* d_in, const int* in_sizes, int n_in,
                              void* d_out, int out_size) {
    const float* pts  = (const float*)d_in[0];   // (N, 3) float32
    const float* quat = (const float*)d_in[1];   // (N, 4) float32
    float* out = (float*)d_out;                  // (N, 3, 3) float32

    gauss_fused<<<NB, TPB>>>(pts, quat, out);
}

// round 8
// speedup vs baseline: 1.3536x; 1.3536x over previous
#include <cuda_runtime.h>
#include <cuda_bf16.h>
#include <math.h>

// Fixed shapes: N = 12288
#define NPTS  12288
#define M     20           // cells per axis in warped (~uniform) space
#define M3    8000
#define FINF  (3.0e38f)
#define FULLMASK 0xFFFFFFFFu

// Device scratch (no allocations). g_hist is zero at module load; the scan
// kernel re-zeroes it every run (replay-invariant).
__device__ float4 g_sorted[NPTS];     // cell-sorted {x,y,z, bitcast(origIdx)}
__device__ int    g_hist[M3];
__device__ int    g_cursor[M3];
__device__ int    g_cellStart[M3 + 1];
__device__ int    g_cellOf[NPTS];

// Cheap monotone quantile map (logistic approx of gaussian CDF).
// Only monotonicity + rough uniformity matter; identical at every use site.
__device__ __forceinline__ int binf(float x) {
    float e = exp2f(-2.4554f * x);          // 2^(-1.702x/ln2)
    float F = 1.0f / (1.0f + e);            // in (0,1)
    int c = (int)(F * 20.0f);
    return min(max(c, 0), M - 1);
}

// ascending insert of d into m1<=m2<=m3
__device__ __forceinline__ void ins3(float d, float& m1, float& m2, float& m3) {
    float t1 = fmaxf(d, m1);  m1 = fminf(d, m1);
    float t2 = fmaxf(t1, m2); m2 = fminf(t1, m2);
    m3 = fminf(t2, m3);
}

// multiset-merge two ascending sorted-3 lists, keep 3 smallest
__device__ __forceinline__ void merge3asc(float& m1, float& m2, float& m3,
                                          float s1, float s2, float s3) {
    float a = fminf(m1, s1), b = fmaxf(m1, s1);
    float c = fminf(m2, s2);
    float e = fminf(m3, s3);
    float t = fmaxf(b, c);
    m1 = a; m2 = fminf(b, c); m3 = fminf(t, e);
}

// ---- K1: bin points ------------------------------------------------------
__global__ void bin_kernel(const float* __restrict__ pts) {
    int i = blockIdx.x * blockDim.x + threadIdx.x;
    if (i >= NPTS) return;
    float x = pts[3 * i + 0], y = pts[3 * i + 1], z = pts[3 * i + 2];
    int c = (binf(z) * M + binf(y)) * M + binf(x);
    g_cellOf[i] = c;
    atomicAdd(&g_hist[c], 1);
}

// ---- K2: exclusive scan over 8000 cells (1 block); re-zeroes g_hist ------
#define SCAN_T 256
#define SCAN_C 32          // 256*32 = 8192 >= M3
__global__ __launch_bounds__(SCAN_T)
void scan_kernel() {
    __shared__ int sh[SCAN_T];
    int tid = threadIdx.x;
    int base = tid * SCAN_C;
    int h[SCAN_C];
    int sum = 0;
    #pragma unroll
    for (int k = 0; k < SCAN_C; ++k) {
        int c = base + k;
        h[k] = (c < M3) ? g_hist[c] : 0;
        sum += h[k];
    }
    sh[tid] = sum;
    __syncthreads();
    for (int off = 1; off < SCAN_T; off <<= 1) {
        int t = (tid >= off) ? sh[tid - off] : 0;
        __syncthreads();
        sh[tid] += t;
        __syncthreads();
    }
    int run = sh[tid] - sum;
    #pragma unroll
    for (int k = 0; k < SCAN_C; ++k) {
        int c = base + k;
        if (c < M3) {
            g_hist[c]      = 0;       // restore zero-invariant for replay
            g_cellStart[c] = run;
            g_cursor[c]    = run;
            run += h[k];
        }
    }
    if (tid == 0) g_cellStart[M3] = NPTS;
}

// ---- K3: scatter into cell-sorted order ----------------------------------
__global__ void scatter_kernel(const float* __restrict__ pts) {
    int i = blockIdx.x * blockDim.x + threadIdx.x;
    if (i >= NPTS) return;
    int c = g_cellOf[i];
    int pos = atomicAdd(&g_cursor[c], 1);
    g_sorted[pos] = make_float4(pts[3 * i + 0], pts[3 * i + 1], pts[3 * i + 2],
                                __int_as_float(i));
}

// ---- K4: 8-lane-team exact 3-NN + covariance -----------------------------
// 8 lanes cooperate per point; 4 teams per warp; 3072 warps on chip.
// Per-lane triples are kept private through BOTH phases; exactly one
// multiset reduce at the end (each candidate counted exactly once).
__global__ __launch_bounds__(256)
void nn_cov_kernel(const float* __restrict__ quat, float* __restrict__ out) {
    const int lane  = threadIdx.x & 31;
    const int lane8 = lane & 7;
    const int p = (blockIdx.x * 256 + threadIdx.x) >> 3;   // point (sorted pos)

    const float4 me = g_sorted[p];
    const float x = me.x, y = me.y, z = me.z;
    const int myi = __float_as_int(me.w);

    const int cx = binf(x), cy = binf(y), cz = binf(z);
    const int lxT = max(cx - 1, 0), hxT = min(cx + 1, M - 1);
    const int lyT = max(cy - 1, 0), hyT = min(cy + 1, M - 1);
    const int lzT = max(cz - 1, 0), hzT = min(cz + 1, M - 1);

    float m1 = FINF, m2 = FINF, m3 = FINF;   // per-lane top-3 (ascending d^2)

    // ---- Phase A: 9 fixed rows (z,y), lanes stride x-contiguous segment --
    #pragma unroll
    for (int dz = -1; dz <= 1; ++dz) {
        #pragma unroll
        for (int dy = -1; dy <= 1; ++dy) {
            int zz = cz + dz, yy = cy + dy;
            bool valid = (zz >= 0) && (zz < M) && (yy >= 0) && (yy < M);
            int a0 = 0, a1 = 0;
            if (valid) {
                int rowbase = (zz * M + yy) * M;
                a0 = g_cellStart[rowbase + lxT];
                a1 = g_cellStart[rowbase + hxT + 1];
            }
            for (int t = a0 + lane8; t < a1; t += 8) {
                float4 q = g_sorted[t];
                if (__float_as_int(q.w) != myi) {
                    float dx = x - q.x, dyv = y - q.y, dzv = z - q.z;
                    ins3(fmaf(dzv, dzv, fmaf(dyv, dyv, dx * dx)), m1, m2, m3);
                }
            }
        }
    }

    // Bound-only reduce into a SEPARATE copy (per-lane m-triples untouched).
    float r1 = m1, r2 = m2, r3 = m3;
    #pragma unroll
    for (int off = 4; off >= 1; off >>= 1) {
        float s1 = __shfl_xor_sync(FULLMASK, r1, off, 8);
        float s2 = __shfl_xor_sync(FULLMASK, r2, off, 8);
        float s3 = __shfl_xor_sync(FULLMASK, r3, off, 8);
        merge3asc(r1, r2, r3, s1, s2, s3);
    }

    // ---- Phase B: exactness pass over ball-box minus scanned box ----
    // (<3 found => r3=FINF => binf saturates => full-grid scan minus 27-box)
    {
        float rad = sqrtf(r3) * 1.0001f;
        int nlx = binf(x - rad), nhx = binf(x + rad);
        int nly = binf(y - rad), nhy = binf(y + rad);
        int nlz = binf(z - rad), nhz = binf(z + rad);
        bool covered = (nlx >= lxT) && (nhx <= hxT) && (nly >= lyT) &&
                       (nhy <= hyT) && (nlz >= lzT) && (nhz <= hzT);
        if (!covered) {
            for (int zz = nlz; zz <= nhz; ++zz) {
                for (int yy = nly; yy <= nhy; ++yy) {
                    int rowbase = (zz * M + yy) * M;
                    bool inRow = (zz >= lzT && zz <= hzT &&
                                  yy >= lyT && yy <= hyT);
                    int a = nlx, bb = inRow ? min(lxT - 1, nhx) : nhx;
                    for (int pass = 0; pass < 2; ++pass) {
                        if (a <= bb) {
                            int s0 = g_cellStart[rowbase + a];
                            int e0 = g_cellStart[rowbase + bb + 1];
                            for (int t = s0 + lane8; t < e0; t += 8) {
                                float4 q = g_sorted[t];
                                if (__float_as_int(q.w) != myi) {
                                    float dx = x - q.x, dyv = y - q.y,
                                          dzv = z - q.z;
                                    ins3(fmaf(dzv, dzv,
                                              fmaf(dyv, dyv, dx * dx)),
                                         m1, m2, m3);
                                }
                            }
                        }
                        if (!inRow) break;
                        a = max(hxT + 1, nlx); bb = nhx;
                    }
                }
            }
        }
    }

    // ---- single final multiset reduce over per-lane triples ----
    #pragma unroll
    for (int off = 4; off >= 1; off >>= 1) {
        float s1 = __shfl_xor_sync(FULLMASK, m1, off, 8);
        float s2 = __shfl_xor_sync(FULLMASK, m2, off, 8);
        float s3 = __shfl_xor_sync(FULLMASK, m3, off, 8);
        merge3asc(m1, m2, m3, s1, s2, s3);
    }

    if (lane8 != 0) return;

    // ---- scale + covariance (one lane per point) ----
    float d1 = sqrtf(m1), d2s = sqrtf(m2), d3s = sqrtf(m3);
    float mean = (d1 + d2s + d3s) * (1.0f / 3.0f);
    float s = 0.001f * fmaxf(mean, 1e-5f);

    float qr = quat[4 * myi + 0];
    float qx = quat[4 * myi + 1];
    float qy = quat[4 * myi + 2];
    float qz = quat[4 * myi + 3];
    float inv = rsqrtf(qr * qr + qx * qx + qy * qy + qz * qz);
    qr *= inv; qx *= inv; qy *= inv; qz *= inv;

    float R00 = 1.0f - 2.0f * (qy * qy + qz * qz);
    float R01 = 2.0f * (qx * qy - qr * qz);
    float R02 = 2.0f * (qx * qz + qr * qy);
    float R10 = 2.0f * (qx * qy + qr * qz);
    float R11 = 1.0f - 2.0f * (qx * qx + qz * qz);
    float R12 = 2.0f * (qy * qz - qr * qx);
    float R20 = 2.0f * (qx * qz - qr * qy);
    float R21 = 2.0f * (qy * qz + qr * qx);
    float R22 = 1.0f - 2.0f * (qx * qx + qy * qy);

    float M00 = s * R00, M01 = s * R01, M02 = s * R02;
    float M10 = s * R10, M11 = s * R11, M12 = s * R12;
    float M20 = s * R20, M21 = s * R21, M22 = s * R22;

    float c00 = M00 * M00 + M01 * M01 + M02 * M02;
    float c01 = M00 * M10 + M01 * M11 + M02 * M12;
    float c02 = M00 * M20 + M01 * M21 + M02 * M22;
    float c11 = M10 * M10 + M11 * M11 + M12 * M12;
    float c12 = M10 * M20 + M11 * M21 + M12 * M22;
    float c22 = M20 * M20 + M21 * M21 + M22 * M22;

    float* o = out + (size_t)myi * 9;
    o[0] = c00; o[1] = c01; o[2] = c02;
    o[3] = c01; o[4] = c11; o[5] = c12;
    o[6] = c02; o[7] = c12; o[8] = c22;
}

extern "C" void kernel_launch(void* const* d_in, const int* in_sizes, int n_in,
                              void* d_out, int out_size) {
    const float* pts  = (const float*)d_in[0];   // (N, 3) float32
    const float* quat = (const float*)d_in[1];   // (N, 4) float32
    float* out = (float*)d_out;                  // (N, 3, 3) float32

    bin_kernel    <<<(NPTS + 255) / 256, 256>>>(pts);
    scan_kernel   <<<1, SCAN_T>>>();
    scatter_kernel<<<(NPTS + 255) / 256, 256>>>(pts);
    nn_cov_kernel <<<(NPTS * 8) / 256, 256>>>(quat, out);
}

// round 10
// speedup vs baseline: 1.7510x; 1.2936x over previous
#include <cuda_runtime.h>
#include <cuda_bf16.h>
#include <math.h>

// Fixed shapes: N = 12288
#define NPTS   12288
#define M      20            // z/y/x bins per axis in warped (~uniform) space
#define M3     8000
#define TILE   256           // i's per tile (contiguous sorted positions)
#define NTILE  48            // NPTS / TILE
#define CH     7             // chunk-blocks per tile (strided, exact for any range)
#define CHUNK  384           // j's per staged chunk
#define FINF   (3.0e38f)
#define NEG_BIG (-1.0e30f)
#define FULLMASK 0xFFFFFFFFu

// Device scratch (no allocations). g_hist zero at load; scan re-zeroes it.
__device__ float4 g_sorted[NPTS];     // cell-sorted {x,y,z, bitcast(origIdx)}
__device__ int    g_hist[M3];
__device__ int    g_cursor[M3];
__device__ int    g_cellStart[M3 + 1];
__device__ int    g_cellOf[NPTS];
__device__ float4 g_cand[CH * NPTS];  // per (chunk-block, i) sorted-desc top-4 of u
__device__ int    g_cnt[NTILE];       // merge arrival counters (reset by merger)
__device__ int    g_failCnt;          // reset by bin_kernel each run
__device__ int    g_failList[NPTS];

// Cheap monotone quantile map (logistic approx of gaussian CDF). Must be the
// SAME function at every use site (binning and coverage check).
__device__ __forceinline__ int binf(float x) {
    float e = exp2f(-2.4554f * x);
    float F = 1.0f / (1.0f + e);
    int c = (int)(F * 20.0f);
    return min(max(c, 0), M - 1);
}

// ---- selection networks (validated R2/R3/R8) -----------------------------
__device__ __forceinline__ void sort4_full(float u0, float u1, float u2, float u3,
                                           float& s1, float& s2, float& s3, float& s4) {
    float p1 = fmaxf(u0, u1), p2 = fminf(u0, u1);
    float q1 = fmaxf(u2, u3), q2 = fminf(u2, u3);
    s1 = fmaxf(p1, q1);
    float x = fminf(p1, q1);
    float y = fmaxf(p2, q2);
    s2 = fmaxf(x, y);
    s3 = fminf(x, y);
    s4 = fminf(p2, q2);
}

// merge sorted-desc 4-lists, keep top-4
__device__ __forceinline__ void merge4(float& m1, float& m2, float& m3, float& m4,
                                       float s1, float s2, float s3, float s4) {
    float a = fmaxf(m1, s1), b = fminf(m1, s1);
    float c = fmaxf(m2, s2), d = fminf(m2, s2);
    float e = fmaxf(m3, s3);
    float g = fmaxf(m4, s4);
    float t  = fminf(b, c);
    float r2 = fmaxf(b, c);
    float r3 = fmaxf(t, e);
    float l1 = fminf(t, e);
    m1 = a; m2 = r2; m3 = r3;
    m4 = fmaxf(fmaxf(l1, d), g);
}

// ascending insert of d into m1<=m2<=m3
__device__ __forceinline__ void ins3(float d, float& m1, float& m2, float& m3) {
    float t1 = fmaxf(d, m1);  m1 = fminf(d, m1);
    float t2 = fmaxf(t1, m2); m2 = fminf(t1, m2);
    m3 = fminf(t2, m3);
}

// merge two ascending sorted-3 lists, keep 3 smallest
__device__ __forceinline__ void merge3asc(float& m1, float& m2, float& m3,
                                          float s1, float s2, float s3) {
    float a = fminf(m1, s1), b = fmaxf(m1, s1);
    float c = fminf(m2, s2);
    float e = fminf(m3, s3);
    float t = fmaxf(b, c);
    m1 = a; m2 = fminf(b, c); m3 = fminf(t, e);
}

__device__ __forceinline__ void write_cov(float m1a, float m2a, float m3a,
                                          int myi, const float* __restrict__ quat,
                                          float* __restrict__ out) {
    // m1a<=m2a<=m3a are the three smallest squared distances
    float d1 = sqrtf(m1a), d2s = sqrtf(m2a), d3s = sqrtf(m3a);
    float mean = (d1 + d2s + d3s) * (1.0f / 3.0f);
    float s = 0.001f * fmaxf(mean, 1e-5f);

    float qr = quat[4 * myi + 0];
    float qx = quat[4 * myi + 1];
    float qy = quat[4 * myi + 2];
    float qz = quat[4 * myi + 3];
    float inv = rsqrtf(qr * qr + qx * qx + qy * qy + qz * qz);
    qr *= inv; qx *= inv; qy *= inv; qz *= inv;

    float R00 = 1.0f - 2.0f * (qy * qy + qz * qz);
    float R01 = 2.0f * (qx * qy - qr * qz);
    float R02 = 2.0f * (qx * qz + qr * qy);
    float R10 = 2.0f * (qx * qy + qr * qz);
    float R11 = 1.0f - 2.0f * (qx * qx + qz * qz);
    float R12 = 2.0f * (qy * qz - qr * qx);
    float R20 = 2.0f * (qx * qz - qr * qy);
    float R21 = 2.0f * (qy * qz + qr * qx);
    float R22 = 1.0f - 2.0f * (qx * qx + qy * qy);

    float M00 = s * R00, M01 = s * R01, M02 = s * R02;
    float M10 = s * R10, M11 = s * R11, M12 = s * R12;
    float M20 = s * R20, M21 = s * R21, M22 = s * R22;

    float c00 = M00 * M00 + M01 * M01 + M02 * M02;
    float c01 = M00 * M10 + M01 * M11 + M02 * M12;
    float c02 = M00 * M20 + M01 * M21 + M02 * M22;
    float c11 = M10 * M10 + M11 * M11 + M12 * M12;
    float c12 = M10 * M20 + M11 * M21 + M12 * M22;
    float c22 = M20 * M20 + M21 * M21 + M22 * M22;

    float* o = out + (size_t)myi * 9;
    o[0] = c00; o[1] = c01; o[2] = c02;
    o[3] = c01; o[4] = c11; o[5] = c12;
    o[6] = c02; o[7] = c12; o[8] = c22;
}

// ---- K1: bin (also resets fail counter for this run) ---------------------
__global__ void bin_kernel(const float* __restrict__ pts) {
    int i = blockIdx.x * blockDim.x + threadIdx.x;
    if (i == 0) g_failCnt = 0;
    if (i >= NPTS) return;
    float x = pts[3 * i + 0], y = pts[3 * i + 1], z = pts[3 * i + 2];
    int c = (binf(z) * M + binf(y)) * M + binf(x);
    g_cellOf[i] = c;
    atomicAdd(&g_hist[c], 1);
}

// ---- K2: exclusive scan over cells (1 block); re-zeroes g_hist -----------
#define SCAN_T 256
#define SCAN_C 32
__global__ __launch_bounds__(SCAN_T)
void scan_kernel() {
    __shared__ int sh[SCAN_T];
    int tid = threadIdx.x;
    int base = tid * SCAN_C;
    int h[SCAN_C];
    int sum = 0;
    #pragma unroll
    for (int k = 0; k < SCAN_C; ++k) {
        int c = base + k;
        h[k] = (c < M3) ? g_hist[c] : 0;
        sum += h[k];
    }
    sh[tid] = sum;
    __syncthreads();
    for (int off = 1; off < SCAN_T; off <<= 1) {
        int t = (tid >= off) ? sh[tid - off] : 0;
        __syncthreads();
        sh[tid] += t;
        __syncthreads();
    }
    int run = sh[tid] - sum;
    #pragma unroll
    for (int k = 0; k < SCAN_C; ++k) {
        int c = base + k;
        if (c < M3) {
            g_hist[c]      = 0;
            g_cellStart[c] = run;
            g_cursor[c]    = run;
            run += h[k];
        }
    }
    if (tid == 0) g_cellStart[M3] = NPTS;
}

// ---- K3: scatter into cell-sorted order ----------------------------------
__global__ void scatter_kernel(const float* __restrict__ pts) {
    int i = blockIdx.x * blockDim.x + threadIdx.x;
    if (i >= NPTS) return;
    int c = g_cellOf[i];
    int pos = atomicAdd(&g_cursor[c], 1);
    g_sorted[pos] = make_float4(pts[3 * i + 0], pts[3 * i + 1], pts[3 * i + 2],
                                __int_as_float(i));
}

// ---- K4: z-slab-pruned brute force + fused merge + coverage check --------
// grid (NTILE, CH). Each block: tile's j-range = slabs [ztmin-1, ztmax+1]
// (contiguous in sorted order); strided CHUNK windows; top-4 of
// u = p.q - 0.5|q|^2 (self = strict max, dropped at merge).
__global__ __launch_bounds__(256)
void chunk_kernel(const float* __restrict__ quat, float* __restrict__ out) {
    __shared__ float4 sh[CHUNK];
    __shared__ int sMin[256], sMax[256];

    const int tid  = threadIdx.x;
    const int tile = blockIdx.x;
    const int i    = tile * TILE + tid;

    const float4 me = g_sorted[i];
    const float xi = me.x, yi = me.y, zi = me.z;

    // block-uniform z-range of this tile
    int zb = binf(zi);
    sMin[tid] = zb; sMax[tid] = zb;
    __syncthreads();
    for (int off = 128; off >= 1; off >>= 1) {
        if (tid < off) {
            sMin[tid] = min(sMin[tid], sMin[tid + off]);
            sMax[tid] = max(sMax[tid], sMax[tid + off]);
        }
        __syncthreads();
    }
    const int zlo = max(sMin[0] - 1, 0);
    const int zhi = min(sMax[0] + 1, M - 1);
    const int jlo = g_cellStart[zlo * (M * M)];
    const int jhi = g_cellStart[(zhi + 1) * (M * M)];
    const int R   = jhi - jlo;

    float m1 = NEG_BIG, m2 = NEG_BIG, m3 = NEG_BIG, m4 = NEG_BIG;

    for (int base = blockIdx.y * CHUNK; base < R; base += CH * CHUNK) {
        const int len = min(CHUNK, R - base);
        __syncthreads();                       // WAR guard vs previous chunk
        for (int t = tid; t < CHUNK; t += 256) {
            if (t < len) {
                float4 q = g_sorted[jlo + base + t];
                q.w = 0.5f * (q.x * q.x + q.y * q.y + q.z * q.z);
                sh[t] = q;
            } else {
                sh[t] = make_float4(0.0f, 0.0f, 0.0f, FINF);   // u = -huge
            }
        }
        __syncthreads();
        #pragma unroll 2
        for (int t = 0; t < CHUNK; t += 4) {
            float4 p0 = sh[t], p1 = sh[t + 1], p2 = sh[t + 2], p3 = sh[t + 3];
            float u0 = fmaf(zi, p0.z, fmaf(yi, p0.y, fmaf(xi, p0.x, -p0.w)));
            float u1 = fmaf(zi, p1.z, fmaf(yi, p1.y, fmaf(xi, p1.x, -p1.w)));
            float u2 = fmaf(zi, p2.z, fmaf(yi, p2.y, fmaf(xi, p2.x, -p2.w)));
            float u3 = fmaf(zi, p3.z, fmaf(yi, p3.y, fmaf(xi, p3.x, -p3.w)));
            float s1, s2, s3, s4;
            sort4_full(u0, u1, u2, u3, s1, s2, s3, s4);
            merge4(m1, m2, m3, m4, s1, s2, s3, s4);
        }
    }

    g_cand[blockIdx.y * NPTS + i] = make_float4(m1, m2, m3, m4);

    // ---- fused merge: last-arriving block of this tile ----
    __threadfence();
    __shared__ int sLast;
    if (tid == 0)
        sLast = (atomicAdd(&g_cnt[tile], 1) == CH - 1) ? 1 : 0;
    __syncthreads();
    if (!sLast) return;
    __threadfence();

    float4 c0 = g_cand[0 * NPTS + i];
    float w1 = c0.x, w2 = c0.y, w3 = c0.z, w4 = c0.w;
    #pragma unroll
    for (int s = 1; s < CH; ++s) {
        float4 cc = g_cand[s * NPTS + i];
        merge4(w1, w2, w3, w4, cc.x, cc.y, cc.z, cc.w);
    }
    // w1 == u_self (strict global max within range); NNs are w2..w4.
    const float sqi = xi * xi + yi * yi + zi * zi;
    float e1 = fmaxf(fmaf(-2.0f, w2, sqi), 0.0f);   // d^2 ascending
    float e2 = fmaxf(fmaf(-2.0f, w3, sqi), 0.0f);
    float e3 = fmaxf(fmaf(-2.0f, w4, sqi), 0.0f);
    float d3 = sqrtf(e3);

    // exactness: ball of radius d3 must lie within scanned z-slabs
    if (binf(zi - d3) >= zlo && binf(zi + d3) <= zhi) {
        write_cov(e1, e2, e3, __float_as_int(me.w), quat, out);
    } else {
        int pos = atomicAdd(&g_failCnt, 1);
        g_failList[pos] = i;                   // fallback kernel finishes it
    }

    if (tid == 0) g_cnt[tile] = 0;             // reset for next graph replay
}

// ---- K5: fallback — warp-per-point full brute force (rare) ---------------
__global__ __launch_bounds__(256)
void fallback_kernel(const float* __restrict__ quat, float* __restrict__ out) {
    const int gw   = (blockIdx.x * 256 + threadIdx.x) >> 5;
    const int lane = threadIdx.x & 31;
    const int nf   = g_failCnt;

    for (int f = gw; f < nf; f += (NTILE * 8)) {
        const int p = g_failList[f];
        const float4 me = g_sorted[p];
        float m1 = FINF, m2 = FINF, m3 = FINF;
        for (int t = lane; t < NPTS; t += 32) {
            if (t == p) continue;
            float4 q = g_sorted[t];
            float dx = me.x - q.x, dy = me.y - q.y, dz = me.z - q.z;
            ins3(fmaf(dz, dz, fmaf(dy, dy, dx * dx)), m1, m2, m3);
        }
        #pragma unroll
        for (int off = 16; off >= 1; off >>= 1) {
            float s1 = __shfl_xor_sync(FULLMASK, m1, off);
            float s2 = __shfl_xor_sync(FULLMASK, m2, off);
            float s3 = __shfl_xor_sync(FULLMASK, m3, off);
            merge3asc(m1, m2, m3, s1, s2, s3);
        }
        if (lane == 0)
            write_cov(m1, m2, m3, __float_as_int(me.w), quat, out);
    }
}

extern "C" void kernel_launch(void* const* d_in, const int* in_sizes, int n_in,
                              void* d_out, int out_size) {
    const float* pts  = (const float*)d_in[0];   // (N, 3) float32
    const float* quat = (const float*)d_in[1];   // (N, 4) float32
    float* out = (float*)d_out;                  // (N, 3, 3) float32

    bin_kernel     <<<(NPTS + 255) / 256, 256>>>(pts);
    scan_kernel    <<<1, SCAN_T>>>();
    scatter_kernel <<<(NPTS + 255) / 256, 256>>>(pts);
    dim3 grid(NTILE, CH);
    chunk_kernel   <<<grid, 256>>>(quat, (float*)d_out);
    fallback_kernel<<<NTILE, 256>>>(quat, (float*)d_out);
}

// round 11
// speedup vs baseline: 2.9779x; 1.7007x over previous
#include <cuda_runtime.h>
#include <cuda_bf16.h>
#include <math.h>

// Fixed shapes: N = 12288
#define NPTS   12288
#define M      20            // bins per axis in warped (~uniform) space
#define M3     8000
#define TILE   256           // i's per tile (contiguous sorted positions)
#define NTILE  48            // NPTS / TILE
#define CH     10            // chunk-blocks per tile (strided, exact for any range)
#define CHUNK  256           // j's per staged chunk
#define FINF   (3.0e38f)
#define NEG_BIG (-1.0e30f)
#define FULLMASK 0xFFFFFFFFu

// Device scratch (no allocations). g_hist zero at load; scan re-zeroes it.
__device__ float4 g_sorted[NPTS];     // cell-sorted {x,y,z, bitcast(origIdx)}
__device__ int    g_hist[M3];
__device__ int    g_cursor[M3];
__device__ int    g_cellStart[M3 + 1];
__device__ int    g_cellOf[NPTS];
__device__ float4 g_cand[CH * NPTS];  // per (chunk-block, i) sorted-desc top-4 of u
__device__ int    g_cnt[NTILE];       // merge arrival counters (reset by merger)
__device__ int    g_failCnt;          // reset by bin_kernel each run
__device__ int    g_failList[NPTS];
__device__ float  g_failRad[NPTS];

// Cheap monotone quantile map (logistic approx of gaussian CDF). Must be the
// SAME function at every use site (binning and coverage check).
__device__ __forceinline__ int binf(float x) {
    float e = exp2f(-2.4554f * x);
    float F = 1.0f / (1.0f + e);
    int c = (int)(F * 20.0f);
    return min(max(c, 0), M - 1);
}

// ---- selection networks (validated R2/R3/R10) ----------------------------
__device__ __forceinline__ void sort4_full(float u0, float u1, float u2, float u3,
                                           float& s1, float& s2, float& s3, float& s4) {
    float p1 = fmaxf(u0, u1), p2 = fminf(u0, u1);
    float q1 = fmaxf(u2, u3), q2 = fminf(u2, u3);
    s1 = fmaxf(p1, q1);
    float x = fminf(p1, q1);
    float y = fmaxf(p2, q2);
    s2 = fmaxf(x, y);
    s3 = fminf(x, y);
    s4 = fminf(p2, q2);
}

// merge sorted-desc 4-lists, keep top-4
__device__ __forceinline__ void merge4(float& m1, float& m2, float& m3, float& m4,
                                       float s1, float s2, float s3, float s4) {
    float a = fmaxf(m1, s1), b = fminf(m1, s1);
    float c = fmaxf(m2, s2), d = fminf(m2, s2);
    float e = fmaxf(m3, s3);
    float g = fmaxf(m4, s4);
    float t  = fminf(b, c);
    float r2 = fmaxf(b, c);
    float r3 = fmaxf(t, e);
    float l1 = fminf(t, e);
    m1 = a; m2 = r2; m3 = r3;
    m4 = fmaxf(fmaxf(l1, d), g);
}

// ascending insert of d into m1<=m2<=m3
__device__ __forceinline__ void ins3(float d, float& m1, float& m2, float& m3) {
    float t1 = fmaxf(d, m1);  m1 = fminf(d, m1);
    float t2 = fmaxf(t1, m2); m2 = fminf(t1, m2);
    m3 = fminf(t2, m3);
}

// merge two ascending sorted-3 lists, keep 3 smallest
__device__ __forceinline__ void merge3asc(float& m1, float& m2, float& m3,
                                          float s1, float s2, float s3) {
    float a = fminf(m1, s1), b = fmaxf(m1, s1);
    float c = fminf(m2, s2);
    float e = fminf(m3, s3);
    float t = fmaxf(b, c);
    m1 = a; m2 = fminf(b, c); m3 = fminf(t, e);
}

__device__ __forceinline__ void write_cov(float m1a, float m2a, float m3a,
                                          int myi, const float* __restrict__ quat,
                                          float* __restrict__ out) {
    float d1 = sqrtf(m1a), d2s = sqrtf(m2a), d3s = sqrtf(m3a);
    float mean = (d1 + d2s + d3s) * (1.0f / 3.0f);
    float s = 0.001f * fmaxf(mean, 1e-5f);

    float qr = quat[4 * myi + 0];
    float qx = quat[4 * myi + 1];
    float qy = quat[4 * myi + 2];
    float qz = quat[4 * myi + 3];
    float inv = rsqrtf(qr * qr + qx * qx + qy * qy + qz * qz);
    qr *= inv; qx *= inv; qy *= inv; qz *= inv;

    float R00 = 1.0f - 2.0f * (qy * qy + qz * qz);
    float R01 = 2.0f * (qx * qy - qr * qz);
    float R02 = 2.0f * (qx * qz + qr * qy);
    float R10 = 2.0f * (qx * qy + qr * qz);
    float R11 = 1.0f - 2.0f * (qx * qx + qz * qz);
    float R12 = 2.0f * (qy * qz - qr * qx);
    float R20 = 2.0f * (qx * qz - qr * qy);
    float R21 = 2.0f * (qy * qz + qr * qx);
    float R22 = 1.0f - 2.0f * (qx * qx + qy * qy);

    float M00 = s * R00, M01 = s * R01, M02 = s * R02;
    float M10 = s * R10, M11 = s * R11, M12 = s * R12;
    float M20 = s * R20, M21 = s * R21, M22 = s * R22;

    float c00 = M00 * M00 + M01 * M01 + M02 * M02;
    float c01 = M00 * M10 + M01 * M11 + M02 * M12;
    float c02 = M00 * M20 + M01 * M21 + M02 * M22;
    float c11 = M10 * M10 + M11 * M11 + M12 * M12;
    float c12 = M10 * M20 + M11 * M21 + M12 * M22;
    float c22 = M20 * M20 + M21 * M21 + M22 * M22;

    float* o = out + (size_t)myi * 9;
    o[0] = c00; o[1] = c01; o[2] = c02;
    o[3] = c01; o[4] = c11; o[5] = c12;
    o[6] = c02; o[7] = c12; o[8] = c22;
}

// ---- K1: bin (also resets fail counter for this run) ---------------------
__global__ void bin_kernel(const float* __restrict__ pts) {
    int i = blockIdx.x * blockDim.x + threadIdx.x;
    if (i == 0) g_failCnt = 0;
    if (i >= NPTS) return;
    float x = pts[3 * i + 0], y = pts[3 * i + 1], z = pts[3 * i + 2];
    int c = (binf(z) * M + binf(y)) * M + binf(x);
    g_cellOf[i] = c;
    atomicAdd(&g_hist[c], 1);
}

// ---- K2: exclusive scan over cells (1 block); re-zeroes g_hist -----------
#define SCAN_T 256
#define SCAN_C 32
__global__ __launch_bounds__(SCAN_T)
void scan_kernel() {
    __shared__ int sh[SCAN_T];
    int tid = threadIdx.x;
    int base = tid * SCAN_C;
    int h[SCAN_C];
    int sum = 0;
    #pragma unroll
    for (int k = 0; k < SCAN_C; ++k) {
        int c = base + k;
        h[k] = (c < M3) ? g_hist[c] : 0;
        sum += h[k];
    }
    sh[tid] = sum;
    __syncthreads();
    for (int off = 1; off < SCAN_T; off <<= 1) {
        int t = (tid >= off) ? sh[tid - off] : 0;
        __syncthreads();
        sh[tid] += t;
        __syncthreads();
    }
    int run = sh[tid] - sum;
    #pragma unroll
    for (int k = 0; k < SCAN_C; ++k) {
        int c = base + k;
        if (c < M3) {
            g_hist[c]      = 0;
            g_cellStart[c] = run;
            g_cursor[c]    = run;
            run += h[k];
        }
    }
    if (tid == 0) g_cellStart[M3] = NPTS;
}

// ---- K3: scatter into cell-sorted order ----------------------------------
__global__ void scatter_kernel(const float* __restrict__ pts) {
    int i = blockIdx.x * blockDim.x + threadIdx.x;
    if (i >= NPTS) return;
    int c = g_cellOf[i];
    int pos = atomicAdd(&g_cursor[c], 1);
    g_sorted[pos] = make_float4(pts[3 * i + 0], pts[3 * i + 1], pts[3 * i + 2],
                                __int_as_float(i));
}

// ---- K4: z-slab-pruned brute force + fused merge + coverage check --------
// grid (NTILE, CH). z-bin is monotone along the sorted array, so the tile's
// slab range comes from its first/last points. j-range = slabs
// [ztmin-1, ztmax+1] (contiguous); top-4 of u = p.q - 0.5|q|^2
// (self = strict max, dropped at merge).
__global__ __launch_bounds__(256)
void chunk_kernel(const float* __restrict__ quat, float* __restrict__ out) {
    __shared__ float4 sh[CHUNK];

    const int tid  = threadIdx.x;
    const int tile = blockIdx.x;
    const int i    = tile * TILE + tid;

    const float4 me = g_sorted[i];
    const float xi = me.x, yi = me.y, zi = me.z;

    // block-uniform slab range from tile endpoints (z-bin monotone in sorted order)
    const int ztmin = binf(g_sorted[tile * TILE].z);
    const int ztmax = binf(g_sorted[tile * TILE + TILE - 1].z);
    const int zlo = max(ztmin - 1, 0);
    const int zhi = min(ztmax + 1, M - 1);
    const int jlo = g_cellStart[zlo * (M * M)];
    const int jhi = g_cellStart[(zhi + 1) * (M * M)];
    const int R   = jhi - jlo;

    float m1 = NEG_BIG, m2 = NEG_BIG, m3 = NEG_BIG, m4 = NEG_BIG;

    for (int base = blockIdx.y * CHUNK; base < R; base += CH * CHUNK) {
        const int len = min(CHUNK, R - base);
        __syncthreads();                       // WAR guard vs previous chunk
        if (tid < CHUNK) {
            if (tid < len) {
                float4 q = g_sorted[jlo + base + tid];
                q.w = 0.5f * (q.x * q.x + q.y * q.y + q.z * q.z);
                sh[tid] = q;
            } else {
                sh[tid] = make_float4(0.0f, 0.0f, 0.0f, FINF);   // u = -huge
            }
        }
        __syncthreads();
        #pragma unroll 2
        for (int t = 0; t < CHUNK; t += 4) {
            float4 p0 = sh[t], p1 = sh[t + 1], p2 = sh[t + 2], p3 = sh[t + 3];
            float u0 = fmaf(zi, p0.z, fmaf(yi, p0.y, fmaf(xi, p0.x, -p0.w)));
            float u1 = fmaf(zi, p1.z, fmaf(yi, p1.y, fmaf(xi, p1.x, -p1.w)));
            float u2 = fmaf(zi, p2.z, fmaf(yi, p2.y, fmaf(xi, p2.x, -p2.w)));
            float u3 = fmaf(zi, p3.z, fmaf(yi, p3.y, fmaf(xi, p3.x, -p3.w)));
            float s1, s2, s3, s4;
            sort4_full(u0, u1, u2, u3, s1, s2, s3, s4);
            merge4(m1, m2, m3, m4, s1, s2, s3, s4);
        }
    }

    g_cand[blockIdx.y * NPTS + i] = make_float4(m1, m2, m3, m4);

    // ---- fused merge: last-arriving block of this tile ----
    __threadfence();
    __shared__ int sLast;
    if (tid == 0)
        sLast = (atomicAdd(&g_cnt[tile], 1) == CH - 1) ? 1 : 0;
    __syncthreads();
    if (!sLast) return;
    __threadfence();

    float4 c0 = g_cand[0 * NPTS + i];
    float w1 = c0.x, w2 = c0.y, w3 = c0.z, w4 = c0.w;
    #pragma unroll
    for (int s = 1; s < CH; ++s) {
        float4 cc = g_cand[s * NPTS + i];
        merge4(w1, w2, w3, w4, cc.x, cc.y, cc.z, cc.w);
    }
    // w1 == u_self (strict global max within range); NNs are w2..w4.
    const float sqi = xi * xi + yi * yi + zi * zi;
    float e1 = fmaxf(fmaf(-2.0f, w2, sqi), 0.0f);   // d^2 ascending
    float e2 = fmaxf(fmaf(-2.0f, w3, sqi), 0.0f);
    float e3 = fmaxf(fmaf(-2.0f, w4, sqi), 0.0f);
    float d3 = sqrtf(e3);

    // exactness: ball of radius d3 must lie within scanned z-slabs
    if (binf(zi - d3) >= zlo && binf(zi + d3) <= zhi) {
        write_cov(e1, e2, e3, __float_as_int(me.w), quat, out);
    } else {
        int pos = atomicAdd(&g_failCnt, 1);
        g_failList[pos] = i;                   // fallback kernel finishes it
        g_failRad[pos]  = d3;
    }

    if (tid == 0) g_cnt[tile] = 0;             // reset for next graph replay
}

// ---- K5: fallback — warp-per-point over restricted z-slab range ----------
// Exact: any point closer than current d3 has z in [zi-d3, zi+d3], fully
// inside slabs [binf(zi-d3), binf(zi+d3)] (contiguous in sorted order).
// Fresh top-3 over that range (skip self) = true global top-3.
#define FB_BLOCKS 192
__global__ __launch_bounds__(256)
void fallback_kernel(const float* __restrict__ quat, float* __restrict__ out) {
    const int gw   = (blockIdx.x * 256 + threadIdx.x) >> 5;
    const int lane = threadIdx.x & 31;
    const int nf   = g_failCnt;

    for (int f = gw; f < nf; f += (FB_BLOCKS * 8)) {
        const int p    = g_failList[f];
        const float rad = g_failRad[f];
        const float4 me = g_sorted[p];

        const int zl = binf(me.z - rad);
        const int zh = binf(me.z + rad);
        const int jlo = g_cellStart[zl * (M * M)];
        const int jhi = g_cellStart[(zh + 1) * (M * M)];

        float m1 = FINF, m2 = FINF, m3 = FINF;
        #pragma unroll 4
        for (int t = jlo + lane; t < jhi; t += 32) {
            float4 q = g_sorted[t];
            float dx = me.x - q.x, dy = me.y - q.y, dz = me.z - q.z;
            float d2 = fmaf(dz, dz, fmaf(dy, dy, dx * dx));
            if (t != p) ins3(d2, m1, m2, m3);
        }
        #pragma unroll
        for (int off = 16; off >= 1; off >>= 1) {
            float s1 = __shfl_xor_sync(FULLMASK, m1, off);
            float s2 = __shfl_xor_sync(FULLMASK, m2, off);
            float s3 = __shfl_xor_sync(FULLMASK, m3, off);
            merge3asc(m1, m2, m3, s1, s2, s3);
        }
        if (lane == 0)
            write_cov(m1, m2, m3, __float_as_int(me.w), quat, out);
    }
}

extern "C" void kernel_launch(void* const* d_in, const int* in_sizes, int n_in,
                              void* d_out, int out_size) {
    const float* pts  = (const float*)d_in[0];   // (N, 3) float32
    const float* quat = (const float*)d_in[1];   // (N, 4) float32
    float* out = (float*)d_out;                  // (N, 3, 3) float32

    bin_kernel     <<<(NPTS + 255) / 256, 256>>>(pts);
    scan_kernel    <<<1, SCAN_T>>>();
    scatter_kernel <<<(NPTS + 255) / 256, 256>>>(pts);
    dim3 grid(NTILE, CH);
    chunk_kernel   <<<grid, 256>>>(quat, out);
    fallback_kernel<<<FB_BLOCKS, 256>>>(quat, out);
}

// round 12
// speedup vs baseline: 3.9178x; 1.3156x over previous
#include <cuda_runtime.h>
#include <cuda_bf16.h>
#include <math.h>

// Fixed shapes: N = 12288
#define NPTS   12288
#define NZ     20            // z-slabs (quantile-binned -> ~equal occupancy)
#define TILE   256           // i's per tile (contiguous sorted positions)
#define NTILE  48            // NPTS / TILE
#define CH     16            // chunk-blocks per tile (strided, exact for any R)
#define CHUNK  128           // j's per staged chunk
#define FINF   (3.0e38f)
#define NEG_BIG (-1.0e30f)
#define FULLMASK 0xFFFFFFFFu

// Device scratch (no allocations). g_zhist/g_zcur zero at load; fallback
// re-zeroes them at the end of every run (replay-invariant).
__device__ float4 g_sorted[NPTS];     // z-slab-sorted {x,y,z, bitcast(origIdx)}
__device__ int    g_zbin[NPTS];
__device__ int    g_zhist[NZ];
__device__ int    g_zcur[NZ];
__device__ int    g_zStart[NZ + 1];
__device__ float4 g_cand[CH * NPTS];  // per (chunk-block, i) sorted-desc top-4 of u
__device__ int    g_cnt[NTILE];       // merge arrival counters (reset by merger)
__device__ int    g_failCnt;          // reset by bin_kernel each run
__device__ int    g_failList[NPTS];
__device__ float  g_failRad[NPTS];

// Cheap monotone quantile map (logistic approx of gaussian CDF). Must be the
// SAME function at every use site (binning and coverage checks).
__device__ __forceinline__ int binf(float x) {
    float e = exp2f(-2.4554f * x);
    float F = 1.0f / (1.0f + e);
    int c = (int)(F * 20.0f);
    return min(max(c, 0), NZ - 1);
}

// ---- selection networks (validated R2/R3/R10/R11) ------------------------
__device__ __forceinline__ void sort4_full(float u0, float u1, float u2, float u3,
                                           float& s1, float& s2, float& s3, float& s4) {
    float p1 = fmaxf(u0, u1), p2 = fminf(u0, u1);
    float q1 = fmaxf(u2, u3), q2 = fminf(u2, u3);
    s1 = fmaxf(p1, q1);
    float x = fminf(p1, q1);
    float y = fmaxf(p2, q2);
    s2 = fmaxf(x, y);
    s3 = fminf(x, y);
    s4 = fminf(p2, q2);
}

// merge sorted-desc 4-lists, keep top-4
__device__ __forceinline__ void merge4(float& m1, float& m2, float& m3, float& m4,
                                       float s1, float s2, float s3, float s4) {
    float a = fmaxf(m1, s1), b = fminf(m1, s1);
    float c = fmaxf(m2, s2), d = fminf(m2, s2);
    float e = fmaxf(m3, s3);
    float g = fmaxf(m4, s4);
    float t  = fminf(b, c);
    float r2 = fmaxf(b, c);
    float r3 = fmaxf(t, e);
    float l1 = fminf(t, e);
    m1 = a; m2 = r2; m3 = r3;
    m4 = fmaxf(fmaxf(l1, d), g);
}

// ascending insert of d into m1<=m2<=m3
__device__ __forceinline__ void ins3(float d, float& m1, float& m2, float& m3) {
    float t1 = fmaxf(d, m1);  m1 = fminf(d, m1);
    float t2 = fmaxf(t1, m2); m2 = fminf(t1, m2);
    m3 = fminf(t2, m3);
}

// merge two ascending sorted-3 lists, keep 3 smallest
__device__ __forceinline__ void merge3asc(float& m1, float& m2, float& m3,
                                          float s1, float s2, float s3) {
    float a = fminf(m1, s1), b = fmaxf(m1, s1);
    float c = fminf(m2, s2);
    float e = fminf(m3, s3);
    float t = fmaxf(b, c);
    m1 = a; m2 = fminf(b, c); m3 = fminf(t, e);
}

__device__ __forceinline__ void write_cov(float m1a, float m2a, float m3a,
                                          int myi, const float* __restrict__ quat,
                                          float* __restrict__ out) {
    float d1 = sqrtf(m1a), d2s = sqrtf(m2a), d3s = sqrtf(m3a);
    float mean = (d1 + d2s + d3s) * (1.0f / 3.0f);
    float s = 0.001f * fmaxf(mean, 1e-5f);

    float qr = quat[4 * myi + 0];
    float qx = quat[4 * myi + 1];
    float qy = quat[4 * myi + 2];
    float qz = quat[4 * myi + 3];
    float inv = rsqrtf(qr * qr + qx * qx + qy * qy + qz * qz);
    qr *= inv; qx *= inv; qy *= inv; qz *= inv;

    float R00 = 1.0f - 2.0f * (qy * qy + qz * qz);
    float R01 = 2.0f * (qx * qy - qr * qz);
    float R02 = 2.0f * (qx * qz + qr * qy);
    float R10 = 2.0f * (qx * qy + qr * qz);
    float R11 = 1.0f - 2.0f * (qx * qx + qz * qz);
    float R12 = 2.0f * (qy * qz - qr * qx);
    float R20 = 2.0f * (qx * qz - qr * qy);
    float R21 = 2.0f * (qy * qz + qr * qx);
    float R22 = 1.0f - 2.0f * (qx * qx + qy * qy);

    float M00 = s * R00, M01 = s * R01, M02 = s * R02;
    float M10 = s * R10, M11 = s * R11, M12 = s * R12;
    float M20 = s * R20, M21 = s * R21, M22 = s * R22;

    float c00 = M00 * M00 + M01 * M01 + M02 * M02;
    float c01 = M00 * M10 + M01 * M11 + M02 * M12;
    float c02 = M00 * M20 + M01 * M21 + M02 * M22;
    float c11 = M10 * M10 + M11 * M11 + M12 * M12;
    float c12 = M10 * M20 + M11 * M21 + M12 * M22;
    float c22 = M20 * M20 + M21 * M21 + M22 * M22;

    float* o = out + (size_t)myi * 9;
    o[0] = c00; o[1] = c01; o[2] = c02;
    o[3] = c01; o[4] = c11; o[5] = c12;
    o[6] = c02; o[7] = c12; o[8] = c22;
}

// ---- K1: z-bin (also resets fail counter for this run) -------------------
__global__ void bin_kernel(const float* __restrict__ pts) {
    int i = blockIdx.x * blockDim.x + threadIdx.x;
    if (i == 0) g_failCnt = 0;
    if (i >= NPTS) return;
    int zb = binf(pts[3 * i + 2]);
    g_zbin[i] = zb;
    atomicAdd(&g_zhist[zb], 1);
}

// ---- K2: scatter into z-slab-sorted order (prefix computed in-block) -----
__global__ __launch_bounds__(256)
void scatter_kernel(const float* __restrict__ pts) {
    __shared__ int sStart[NZ + 1];
    if (threadIdx.x == 0) {
        int run = 0;
        #pragma unroll
        for (int zpre = 0; zpre < NZ; ++zpre) {
            sStart[zpre] = run;
            run += g_zhist[zpre];
        }
        sStart[NZ] = run;                      // == NPTS
    }
    __syncthreads();

    // block 0 publishes the prefix for chunk/fallback kernels
    if (blockIdx.x == 0 && threadIdx.x <= NZ)
        g_zStart[threadIdx.x] = sStart[threadIdx.x];

    int i = blockIdx.x * blockDim.x + threadIdx.x;
    if (i >= NPTS) return;
    int zb = g_zbin[i];
    int pos = sStart[zb] + atomicAdd(&g_zcur[zb], 1);
    g_sorted[pos] = make_float4(pts[3 * i + 0], pts[3 * i + 1], pts[3 * i + 2],
                                __int_as_float(i));
}

// ---- K3: z-slab-pruned brute force + fused merge + coverage check --------
// grid (NTILE, CH). z-bin is monotone along the sorted array, so the tile's
// slab range comes from its first/last points. j-range = slabs
// [ztmin-1, ztmax+1] (contiguous); top-4 of u = p.q - 0.5|q|^2
// (self = strict max, dropped at merge).
__global__ __launch_bounds__(256)
void chunk_kernel(const float* __restrict__ quat, float* __restrict__ out) {
    __shared__ float4 sh[CHUNK];

    const int tid  = threadIdx.x;
    const int tile = blockIdx.x;
    const int i    = tile * TILE + tid;

    const float4 me = g_sorted[i];
    const float xi = me.x, yi = me.y, zi = me.z;

    const int ztmin = binf(g_sorted[tile * TILE].z);
    const int ztmax = binf(g_sorted[tile * TILE + TILE - 1].z);
    const int zlo = max(ztmin - 1, 0);
    const int zhi = min(ztmax + 1, NZ - 1);
    const int jlo = g_zStart[zlo];
    const int jhi = g_zStart[zhi + 1];
    const int R   = jhi - jlo;

    float m1 = NEG_BIG, m2 = NEG_BIG, m3 = NEG_BIG, m4 = NEG_BIG;

    for (int base = blockIdx.y * CHUNK; base < R; base += CH * CHUNK) {
        const int len = min(CHUNK, R - base);
        __syncthreads();                       // WAR guard vs previous chunk
        if (tid < CHUNK) {
            if (tid < len) {
                float4 q = g_sorted[jlo + base + tid];
                q.w = 0.5f * (q.x * q.x + q.y * q.y + q.z * q.z);
                sh[tid] = q;
            } else {
                sh[tid] = make_float4(0.0f, 0.0f, 0.0f, FINF);   // u = -huge
            }
        }
        __syncthreads();
        #pragma unroll 2
        for (int t = 0; t < CHUNK; t += 4) {
            float4 p0 = sh[t], p1 = sh[t + 1], p2 = sh[t + 2], p3 = sh[t + 3];
            float u0 = fmaf(zi, p0.z, fmaf(yi, p0.y, fmaf(xi, p0.x, -p0.w)));
            float u1 = fmaf(zi, p1.z, fmaf(yi, p1.y, fmaf(xi, p1.x, -p1.w)));
            float u2 = fmaf(zi, p2.z, fmaf(yi, p2.y, fmaf(xi, p2.x, -p2.w)));
            float u3 = fmaf(zi, p3.z, fmaf(yi, p3.y, fmaf(xi, p3.x, -p3.w)));
            float s1, s2, s3, s4;
            sort4_full(u0, u1, u2, u3, s1, s2, s3, s4);
            merge4(m1, m2, m3, m4, s1, s2, s3, s4);
        }
    }

    g_cand[blockIdx.y * NPTS + i] = make_float4(m1, m2, m3, m4);

    // ---- fused merge: last-arriving block of this tile ----
    __threadfence();
    __shared__ int sLast;
    if (tid == 0)
        sLast = (atomicAdd(&g_cnt[tile], 1) == CH - 1) ? 1 : 0;
    __syncthreads();
    if (!sLast) return;
    __threadfence();

    float4 c0 = g_cand[0 * NPTS + i];
    float w1 = c0.x, w2 = c0.y, w3 = c0.z, w4 = c0.w;
    #pragma unroll
    for (int s = 1; s < CH; ++s) {
        float4 cc = g_cand[s * NPTS + i];
        merge4(w1, w2, w3, w4, cc.x, cc.y, cc.z, cc.w);
    }
    // w1 == u_self (strict global max within range); NNs are w2..w4.
    const float sqi = xi * xi + yi * yi + zi * zi;
    float e1 = fmaxf(fmaf(-2.0f, w2, sqi), 0.0f);   // d^2 ascending
    float e2 = fmaxf(fmaf(-2.0f, w3, sqi), 0.0f);
    float e3 = fmaxf(fmaf(-2.0f, w4, sqi), 0.0f);
    float d3 = sqrtf(e3);

    // exactness: ball of radius d3 must lie within scanned z-slabs
    if (binf(zi - d3) >= zlo && binf(zi + d3) <= zhi) {
        write_cov(e1, e2, e3, __float_as_int(me.w), quat, out);
    } else {
        int pos = atomicAdd(&g_failCnt, 1);
        g_failList[pos] = i;                   // fallback kernel finishes it
        g_failRad[pos]  = d3;
    }

    if (tid == 0) g_cnt[tile] = 0;             // reset for next graph replay
}

// ---- K4: fallback — warp-per-point over restricted z-slab range ----------
// Exact: any point closer than current d3 has z in [zi-d3, zi+d3], fully
// inside slabs [binf(zi-d3), binf(zi+d3)] (contiguous in sorted order).
// Fresh top-3 over that range (skip self) = true global top-3.
#define FB_BLOCKS 192
__global__ __launch_bounds__(256)
void fallback_kernel(const float* __restrict__ quat, float* __restrict__ out) {
    const int gw   = (blockIdx.x * 256 + threadIdx.x) >> 5;
    const int lane = threadIdx.x & 31;
    const int nf   = g_failCnt;

    for (int f = gw; f < nf; f += (FB_BLOCKS * 8)) {
        const int p    = g_failList[f];
        const float rad = g_failRad[f];
        const float4 me = g_sorted[p];

        const int zl = binf(me.z - rad);
        const int zh = binf(me.z + rad);
        const int jlo = g_zStart[zl];
        const int jhi = g_zStart[zh + 1];

        float m1 = FINF, m2 = FINF, m3 = FINF;
        #pragma unroll 4
        for (int t = jlo + lane; t < jhi; t += 32) {
            float4 q = g_sorted[t];
            float dx = me.x - q.x, dy = me.y - q.y, dz = me.z - q.z;
            float d2 = fmaf(dz, dz, fmaf(dy, dy, dx * dx));
            if (t != p) ins3(d2, m1, m2, m3);
        }
        #pragma unroll
        for (int off = 16; off >= 1; off >>= 1) {
            float s1 = __shfl_xor_sync(FULLMASK, m1, off);
            float s2 = __shfl_xor_sync(FULLMASK, m2, off);
            float s3 = __shfl_xor_sync(FULLMASK, m3, off);
            merge3asc(m1, m2, m3, s1, s2, s3);
        }
        if (lane == 0)
            write_cov(m1, m2, m3, __float_as_int(me.w), quat, out);
    }

    // restore zero-invariants for the next graph replay
    if (blockIdx.x == 0 && threadIdx.x < NZ) {
        g_zhist[threadIdx.x] = 0;
        g_zcur[threadIdx.x]  = 0;
    }
}

extern "C" void kernel_launch(void* const* d_in, const int* in_sizes, int n_in,
                              void* d_out, int out_size) {
    const float* pts  = (const float*)d_in[0];   // (N, 3) float32
    const float* quat = (const float*)d_in[1];   // (N, 4) float32
    float* out = (float*)d_out;                  // (N, 3, 3) float32

    bin_kernel     <<<(NPTS + 255) / 256, 256>>>(pts);
    scatter_kernel <<<(NPTS + 255) / 256, 256>>>(pts);
    dim3 grid(NTILE, CH);
    chunk_kernel   <<<grid, 256>>>(quat, out);
    fallback_kernel<<<FB_BLOCKS, 256>>>(quat, out);
}